// round 15
// baseline (speedup 1.0000x reference)
#include <cuda_runtime.h>
#include <math.h>

#define N_MEM   500000
#define D_LAT   512
#define D_Q     768
#define NBINS   4096
#define CAP     1024
#define SIMS_GRID 592                       // 4 blocks/SM * 148
#define SIMS_WARPS (SIMS_GRID * 8)          // 4736
#define CHUNK_ROWS 16
#define NCHUNKS (N_MEM / CHUNK_ROWS)        // 31250
#define FILT_GRID 512
#define RER_GRID 256                        // 32 candidates x 8 j-chunks

__device__ __align__(16) float g_q[D_LAT];
__device__ float g_ss_part[64];
__device__ __align__(16) float g_aj[D_LAT];
__device__ __align__(16) float g_sims[N_MEM];
__device__ unsigned g_hist[NBINS];
__device__ unsigned g_tkey;
__device__ int g_ncand;
__device__ float g_cv[CAP];
__device__ int   g_ci[CAP];
__device__ int   g_cand[32];
__device__ float g_rpart[RER_GRID];
__device__ int g_tick1, g_tick2, g_tick3;
__device__ int g_work;

__device__ __forceinline__ float warp_sum(float v) {
#pragma unroll
    for (int o = 16; o; o >>= 1) v += __shfl_xor_sync(0xffffffffu, v, o);
    return v;
}

// monotonic float->uint key: order-preserving over all floats
__device__ __forceinline__ unsigned mkey(float f) {
    unsigned u = __float_as_uint(f);
    return (u & 0x80000000u) ? ~u : (u | 0x80000000u);
}

// ---------------------------------------------------------------------------
// 1) q = Wp @ query + bp. 64 blocks x 256 thr, warp-per-row (8 rows/block).
//    Also resets g_hist / counters / work ticket for this replay.
__global__ void __launch_bounds__(256) k_proj(const float* __restrict__ query,
                                              const float* __restrict__ Wp,
                                              const float* __restrict__ bp) {
    __shared__ float4 qs[D_Q / 4];
    __shared__ float red[8];
    int t = threadIdx.x, blk = blockIdx.x;
    int gt = blk * 256 + t;
    if (gt < NBINS) g_hist[gt] = 0;
    if (gt == 0) {
        g_ncand = 0; g_tick1 = 0; g_tick2 = 0; g_tick3 = 0;
        g_work = SIMS_WARPS;     // first chunk per warp is its static id
    }
    for (int i = t; i < D_Q / 4; i += 256) qs[i] = ((const float4*)query)[i];
    __syncthreads();
    int w = t >> 5, lane = t & 31;
    int r = blk * 8 + w;
    const float4* p = (const float4*)(Wp + (size_t)r * D_Q);
    float4 a0 = p[lane],        a1 = p[lane + 32],  a2 = p[lane + 64];
    float4 a3 = p[lane + 96],   a4 = p[lane + 128], a5 = p[lane + 160];
    float4 q0 = qs[lane],       q1 = qs[lane + 32], q2 = qs[lane + 64];
    float4 q3 = qs[lane + 96],  q4 = qs[lane + 128], q5 = qs[lane + 160];
    float d = a0.x * q0.x + a0.y * q0.y + a0.z * q0.z + a0.w * q0.w
            + a1.x * q1.x + a1.y * q1.y + a1.z * q1.z + a1.w * q1.w
            + a2.x * q2.x + a2.y * q2.y + a2.z * q2.z + a2.w * q2.w
            + a3.x * q3.x + a3.y * q3.y + a3.z * q3.z + a3.w * q3.w
            + a4.x * q4.x + a4.y * q4.y + a4.z * q4.z + a4.w * q4.w
            + a5.x * q5.x + a5.y * q5.y + a5.z * q5.z + a5.w * q5.w;
    d = warp_sum(d);
    if (lane == 0) {
        float v = d + bp[r];
        g_q[r] = v;
        red[w] = v * v;
    }
    __syncthreads();
    if (t == 0) {
        float s = 0.f;
        for (int i = 0; i < 8; i++) s += red[i];
        g_ss_part[blk] = s;
    }
}

// ---------------------------------------------------------------------------
// 2) sims[i] = dot(mem_i, qn)/(||mem_i||+1e-8). Persistent; DYNAMIC 16-row
//    chunk stealing (double-buffered tickets hide atomic latency; first
//    chunk is the warp's static id). Blocks 0..31 also compute a_j (their
//    late start is absorbed by the stealing). Fused smem histogram; LAST
//    block computes the threshold key.
__global__ void __launch_bounds__(256, 4) k_sims(const float* __restrict__ mem,
                                                 const float* __restrict__ W1,
                                                 const float* __restrict__ b1) {
    __shared__ float4 qsh[D_LAT / 4];
    __shared__ unsigned hist[NBINS];
    __shared__ unsigned part[256];
    __shared__ int is_last;
    int t = threadIdx.x;
    int w = t >> 5, lane = t & 31;

    // --- aj sub-task on blocks 0..31: a_j = b1[j] + dot(q, W1[j,0:512]) ---
    if (blockIdx.x < 32) {
        int j0 = blockIdx.x * 16 + w * 2, j1 = j0 + 1;
        const float4* p0 = (const float4*)(W1 + (size_t)j0 * (2 * D_LAT));
        const float4* p1 = (const float4*)(W1 + (size_t)j1 * (2 * D_LAT));
        float d0 = 0.f, d1 = 0.f;
#pragma unroll
        for (int u = 0; u < 4; u++) {
            float4 a = p0[lane + 32 * u];
            float4 b = p1[lane + 32 * u];
            float4 q = ((const float4*)g_q)[lane + 32 * u];
            d0 += a.x * q.x + a.y * q.y + a.z * q.z + a.w * q.w;
            d1 += b.x * q.x + b.y * q.y + b.z * q.z + b.w * q.w;
        }
        d0 = warp_sum(d0); d1 = warp_sum(d1);
        if (lane == 0) { g_aj[j0] = d0 + b1[j0]; g_aj[j1] = d1 + b1[j1]; }
    }

    float ss = 0.f;
#pragma unroll
    for (int i = 0; i < 64; i++) ss += g_ss_part[i];
    float inv = 1.0f / (sqrtf(ss) + 1e-8f);
    for (int i = t; i < D_LAT / 4; i += 256) {
        float4 q = ((const float4*)g_q)[i];
        q.x *= inv; q.y *= inv; q.z *= inv; q.w *= inv;
        qsh[i] = q;
    }
    for (int i = t; i < NBINS; i += 256) hist[i] = 0;
    __syncthreads();

    int wg = blockIdx.x * 8 + w;
    int cur = wg;                       // static first chunk (no herd)
    while (cur < NCHUNKS) {
        // grab NEXT ticket now; its latency hides under chunk processing
        int nxt;
        if (lane == 0) nxt = atomicAdd(&g_work, 1);
        nxt = __shfl_sync(0xffffffffu, nxt, 0);

        int base0 = cur * CHUNK_ROWS;
#pragma unroll 2
        for (int rr = 0; rr < CHUNK_ROWS; rr += 2) {
            int base = base0 + rr;
            const float4* r0 = (const float4*)(mem + (size_t)base * D_LAT);
            const float4* r1 = (const float4*)(mem + (size_t)(base + 1) * D_LAT);
            float d0 = 0.f, s0 = 0.f, d1 = 0.f, s1 = 0.f;
#pragma unroll
            for (int u = 0; u < 4; u++) {
                float4 a = r0[lane + 32 * u];
                float4 b = r1[lane + 32 * u];
                float4 q = qsh[lane + 32 * u];
                d0 += a.x * q.x + a.y * q.y + a.z * q.z + a.w * q.w;
                s0 += a.x * a.x + a.y * a.y + a.z * a.z + a.w * a.w;
                d1 += b.x * q.x + b.y * q.y + b.z * q.z + b.w * q.w;
                s1 += b.x * b.x + b.y * b.y + b.z * b.z + b.w * b.w;
            }
            d0 = warp_sum(d0); s0 = warp_sum(s0);
            d1 = warp_sum(d1); s1 = warp_sum(s1);
            if (lane == 0) {
                float v0 = d0 / (sqrtf(s0) + 1e-8f);
                float v1 = d1 / (sqrtf(s1) + 1e-8f);
                g_sims[base] = v0;
                g_sims[base + 1] = v1;
                atomicAdd(&hist[mkey(v0) >> 20], 1u);
                atomicAdd(&hist[mkey(v1) >> 20], 1u);
            }
        }
        cur = nxt;
    }
    __syncthreads();
    for (int i = t; i < NBINS; i += 256) {
        unsigned c = hist[i];
        if (c) atomicAdd(&g_hist[i], c);
    }
    __syncthreads();
    if (t == 0) {
        __threadfence();
        is_last = (atomicAdd(&g_tick1, 1) == SIMS_GRID - 1);
    }
    __syncthreads();
    if (!is_last) return;

    // --- threshold epilogue (only last block) ---
    unsigned s16 = 0;
#pragma unroll
    for (int i = 0; i < 16; i++) s16 += g_hist[t * 16 + i];
    part[t] = s16;
    __syncthreads();
    if (w == 0) {
        unsigned c8 = 0;
#pragma unroll
        for (int i = 0; i < 8; i++) c8 += part[lane * 8 + i];
        unsigned suf = c8;
#pragma unroll
        for (int o = 1; o < 32; o <<= 1) {
            unsigned x = __shfl_down_sync(0xffffffffu, suf, o);
            if (lane + o < 32) suf += x;
        }
        unsigned above = __shfl_down_sync(0xffffffffu, suf, 1);
        if (lane == 31) above = 0;
        unsigned mask = __ballot_sync(0xffffffffu, suf >= 32u);
        int Lstar = 31 - __clz(mask);   // highest lane whose suffix >= 32
        if (lane == Lstar) {
            unsigned cum = above;
            int seg = Lstar * 8 + 7;
            for (; seg > Lstar * 8; seg--) {
                if (cum + part[seg] >= 32u) break;
                cum += part[seg];
            }
            int bin = seg * 16 + 15;
            for (; bin > seg * 16; bin--) {
                cum += g_hist[bin];
                if (cum >= 32u) break;
            }
            g_tkey = ((unsigned)bin) << 20;
        }
    }
}

// ---------------------------------------------------------------------------
// 3) filter: compact sims with key >= threshold; LAST block runs the exact
//    stable top-32 select over an smem copy with a single warp.
__global__ void __launch_bounds__(256) k_filter() {
    __shared__ float sv[CAP];
    __shared__ int   si[CAP];
    __shared__ int is_last;
    int t = threadIdx.x, blk = blockIdx.x;
    int w = t >> 5, lane = t & 31;

    unsigned tkey = g_tkey;
    for (int i4 = blk * 256 + t; i4 < N_MEM / 4; i4 += FILT_GRID * 256) {
        float4 v = ((const float4*)g_sims)[i4];
        int i = i4 * 4;
        if (mkey(v.x) >= tkey) { int p = atomicAdd(&g_ncand, 1); if (p < CAP) { g_cv[p] = v.x; g_ci[p] = i; } }
        if (mkey(v.y) >= tkey) { int p = atomicAdd(&g_ncand, 1); if (p < CAP) { g_cv[p] = v.y; g_ci[p] = i + 1; } }
        if (mkey(v.z) >= tkey) { int p = atomicAdd(&g_ncand, 1); if (p < CAP) { g_cv[p] = v.z; g_ci[p] = i + 2; } }
        if (mkey(v.w) >= tkey) { int p = atomicAdd(&g_ncand, 1); if (p < CAP) { g_cv[p] = v.w; g_ci[p] = i + 3; } }
    }
    if (t == 0) {
        __threadfence();
        is_last = (atomicAdd(&g_tick2, 1) == FILT_GRID - 1);
    }
    __syncthreads();
    if (!is_last) return;

    // --- select epilogue: copy survivors to smem once, one warp selects ---
    int n = g_ncand; if (n > CAP) n = CAP;
    for (int i = t; i < n; i += 256) { sv[i] = g_cv[i]; si[i] = g_ci[i]; }
    __syncthreads();
    if (w == 0) {
        for (int r = 0; r < 32; r++) {
            float bv = -1e30f; int bi = 0x7fffffff, bp = -1;
            for (int i = lane; i < n; i += 32) {
                float v = sv[i]; int idx = si[i];
                if (v > bv || (v == bv && idx < bi)) { bv = v; bi = idx; bp = i; }
            }
#pragma unroll
            for (int o = 16; o; o >>= 1) {
                float ov = __shfl_xor_sync(0xffffffffu, bv, o);
                int oi = __shfl_xor_sync(0xffffffffu, bi, o);
                int op = __shfl_xor_sync(0xffffffffu, bp, o);
                if (ov > bv || (ov == bv && oi < bi)) { bv = ov; bi = oi; bp = op; }
            }
            if (lane == 0) {
                g_cand[r] = bi;
                if (bp >= 0) sv[bp] = -1e30f;
            }
            __syncwarp();
        }
    }
}

// ---------------------------------------------------------------------------
// 4) rerank: block = c*8 + chunk (32 candidates x 8 chunks of 64 j).
//    16 warps x 4 j (2-way ILP x 2 iters). LAST block reduces the 8 partials
//    per candidate in fixed order via one PARALLEL smem load of all 256
//    partials, adds b2, and writes the final stable top-16.
__global__ void __launch_bounds__(512) k_rerank(const float* __restrict__ mem,
                                                const float* __restrict__ W1,
                                                const float* __restrict__ W2,
                                                const float* __restrict__ b2,
                                                float* __restrict__ out,
                                                int out_size) {
    __shared__ float4 cs[D_LAT / 4];
    __shared__ float wacc[16];
    __shared__ int is_last;
    int blk = blockIdx.x, t = threadIdx.x;
    int c = blk >> 3, chunk = blk & 7;
    int cidx = g_cand[c];
    for (int i = t; i < D_LAT / 4; i += 512)
        cs[i] = ((const float4*)(mem + (size_t)cidx * D_LAT))[i];
    __syncthreads();
    int w = t >> 5, lane = t & 31;
    float acc = 0.f;
#pragma unroll
    for (int jj = 0; jj < 4; jj += 2) {
        int j0 = chunk * 64 + w * 4 + jj, j1 = j0 + 1;
        const float4* p0 = (const float4*)(W1 + (size_t)j0 * (2 * D_LAT) + D_LAT);
        const float4* p1 = (const float4*)(W1 + (size_t)j1 * (2 * D_LAT) + D_LAT);
        float d0 = 0.f, d1 = 0.f;
#pragma unroll
        for (int u = 0; u < 4; u++) {
            float4 a = p0[lane + 32 * u];
            float4 b = p1[lane + 32 * u];
            float4 q = cs[lane + 32 * u];
            d0 += a.x * q.x + a.y * q.y + a.z * q.z + a.w * q.w;
            d1 += b.x * q.x + b.y * q.y + b.z * q.z + b.w * q.w;
        }
        d0 = warp_sum(d0); d1 = warp_sum(d1);
        if (lane == 0) {
            float h0 = g_aj[j0] + d0; if (h0 > 0.f) acc += h0 * W2[j0];
            float h1 = g_aj[j1] + d1; if (h1 > 0.f) acc += h1 * W2[j1];
        }
    }
    if (lane == 0) wacc[w] = acc;
    __syncthreads();
    if (t == 0) {
        float s = 0.f;
#pragma unroll
        for (int i = 0; i < 16; i++) s += wacc[i];
        g_rpart[blk] = s;
        __threadfence();
        is_last = (atomicAdd(&g_tick3, 1) == RER_GRID - 1);
    }
    __syncthreads();
    if (!is_last) return;

    // --- final epilogue: parallel partial load + fixed-order reduce + top-16
    __shared__ float pr[RER_GRID];
    __shared__ float fsc[32];
    __shared__ int   fid[32];
    if (t < RER_GRID) pr[t] = g_rpart[t];
    __syncthreads();
    if (w == 0) {
        float s = 0.f;
#pragma unroll
        for (int p = 0; p < 8; p++) s += pr[lane * 8 + p];
        fsc[lane] = s + b2[0];
        fid[lane] = g_cand[lane];
        __syncwarp();
        if (lane == 0) {
            for (int r = 0; r < 16; r++) {
                float bv = -1e30f; int bp = 0;
                for (int k = 0; k < 32; k++)
                    if (fsc[k] > bv) { bv = fsc[k]; bp = k; }
                if (r < out_size)      out[r]      = bv;
                if (16 + r < out_size) out[16 + r] = (float)fid[bp];
                fsc[bp] = -1e30f;
            }
        }
    }
}

// ---------------------------------------------------------------------------
extern "C" void kernel_launch(void* const* d_in, const int* in_sizes, int n_in,
                              void* d_out, int out_size) {
    const float* query  = (const float*)d_in[0];
    const float* memory = (const float*)d_in[1];
    const float* Wp     = (const float*)d_in[2];
    const float* bp     = (const float*)d_in[3];
    const float* W1     = (const float*)d_in[4];
    const float* b1     = (const float*)d_in[5];
    const float* W2     = (const float*)d_in[6];
    const float* b2     = (const float*)d_in[7];
    (void)in_sizes; (void)n_in;

    k_proj  <<<64, 256>>>(query, Wp, bp);
    k_sims  <<<SIMS_GRID, 256>>>(memory, W1, b1);
    k_filter<<<FILT_GRID, 256>>>();
    k_rerank<<<RER_GRID, 512>>>(memory, W1, W2, b2, (float*)d_out, out_size);
}

// round 16
// speedup vs baseline: 1.0229x; 1.0229x over previous
#include <cuda_runtime.h>
#include <math.h>

#define N_MEM   500000
#define D_LAT   512
#define D_Q     768
#define NBINS   4096
#define CAP     1024
#define SIMS_GRID 592                       // 4 blocks/SM * 148
#define SIMS_WARPS (SIMS_GRID * 8)          // 4736
#define SIMS_STRIDE (SIMS_WARPS * 2)        // rows per grid-iteration
#define FR_GRID 256                         // 32 candidates x 8 j-chunks

__device__ __align__(16) float g_q[D_LAT];
__device__ float g_ss_part[64];
__device__ __align__(16) float g_aj[D_LAT];
__device__ __align__(16) float g_sims[N_MEM];
__device__ unsigned g_hist[NBINS];
__device__ unsigned g_tkey;
__device__ int g_ncand;
__device__ float g_cv[CAP];
__device__ int   g_ci[CAP];
__device__ int   g_cand[32];
__device__ float g_rpart[FR_GRID];
__device__ int g_tick1, g_tick2, g_tick3;
__device__ int g_flag2;

__device__ __forceinline__ float warp_sum(float v) {
#pragma unroll
    for (int o = 16; o; o >>= 1) v += __shfl_xor_sync(0xffffffffu, v, o);
    return v;
}

// monotonic float->uint key: order-preserving over all floats
__device__ __forceinline__ unsigned mkey(float f) {
    unsigned u = __float_as_uint(f);
    return (u & 0x80000000u) ? ~u : (u | 0x80000000u);
}

// ---------------------------------------------------------------------------
// 1) q = Wp @ query + bp. 64 blocks x 256 thr, warp-per-row (8 rows/block).
//    Also resets g_hist / counters / flag for this replay (graph-replay safe).
__global__ void __launch_bounds__(256) k_proj(const float* __restrict__ query,
                                              const float* __restrict__ Wp,
                                              const float* __restrict__ bp) {
    __shared__ float4 qs[D_Q / 4];
    __shared__ float red[8];
    int t = threadIdx.x, blk = blockIdx.x;
    int gt = blk * 256 + t;
    if (gt < NBINS) g_hist[gt] = 0;
    if (gt == 0) { g_ncand = 0; g_tick1 = 0; g_tick2 = 0; g_tick3 = 0; g_flag2 = 0; }
    for (int i = t; i < D_Q / 4; i += 256) qs[i] = ((const float4*)query)[i];
    __syncthreads();
    int w = t >> 5, lane = t & 31;
    int r = blk * 8 + w;
    const float4* p = (const float4*)(Wp + (size_t)r * D_Q);
    float4 a0 = p[lane],        a1 = p[lane + 32],  a2 = p[lane + 64];
    float4 a3 = p[lane + 96],   a4 = p[lane + 128], a5 = p[lane + 160];
    float4 q0 = qs[lane],       q1 = qs[lane + 32], q2 = qs[lane + 64];
    float4 q3 = qs[lane + 96],  q4 = qs[lane + 128], q5 = qs[lane + 160];
    float d = a0.x * q0.x + a0.y * q0.y + a0.z * q0.z + a0.w * q0.w
            + a1.x * q1.x + a1.y * q1.y + a1.z * q1.z + a1.w * q1.w
            + a2.x * q2.x + a2.y * q2.y + a2.z * q2.z + a2.w * q2.w
            + a3.x * q3.x + a3.y * q3.y + a3.z * q3.z + a3.w * q3.w
            + a4.x * q4.x + a4.y * q4.y + a4.z * q4.z + a4.w * q4.w
            + a5.x * q5.x + a5.y * q5.y + a5.z * q5.z + a5.w * q5.w;
    d = warp_sum(d);
    if (lane == 0) {
        float v = d + bp[r];
        g_q[r] = v;
        red[w] = v * v;
    }
    __syncthreads();
    if (t == 0) {
        float s = 0.f;
        for (int i = 0; i < 8; i++) s += red[i];
        g_ss_part[blk] = s;
    }
}

// ---------------------------------------------------------------------------
// 2) sims[i] = dot(mem_i, qn)/(||mem_i||+1e-8). Persistent, STATIC stripes,
//    2 rows/warp/iter. Blocks 0..31 additionally compute a_j (hidden under
//    the memory pass). Fused smem histogram; LAST block computes threshold.
__global__ void __launch_bounds__(256, 4) k_sims(const float* __restrict__ mem,
                                                 const float* __restrict__ W1,
                                                 const float* __restrict__ b1) {
    __shared__ float4 qsh[D_LAT / 4];
    __shared__ unsigned hist[NBINS];
    __shared__ unsigned part[256];
    __shared__ int is_last;
    int t = threadIdx.x;
    int w = t >> 5, lane = t & 31;

    // --- aj sub-task on blocks 0..31: a_j = b1[j] + dot(q, W1[j,0:512]) ---
    if (blockIdx.x < 32) {
        int j0 = blockIdx.x * 16 + w * 2, j1 = j0 + 1;
        const float4* p0 = (const float4*)(W1 + (size_t)j0 * (2 * D_LAT));
        const float4* p1 = (const float4*)(W1 + (size_t)j1 * (2 * D_LAT));
        float d0 = 0.f, d1 = 0.f;
#pragma unroll
        for (int u = 0; u < 4; u++) {
            float4 a = p0[lane + 32 * u];
            float4 b = p1[lane + 32 * u];
            float4 q = ((const float4*)g_q)[lane + 32 * u];
            d0 += a.x * q.x + a.y * q.y + a.z * q.z + a.w * q.w;
            d1 += b.x * q.x + b.y * q.y + b.z * q.z + b.w * q.w;
        }
        d0 = warp_sum(d0); d1 = warp_sum(d1);
        if (lane == 0) { g_aj[j0] = d0 + b1[j0]; g_aj[j1] = d1 + b1[j1]; }
    }

    float ss = 0.f;
#pragma unroll
    for (int i = 0; i < 64; i++) ss += g_ss_part[i];
    float inv = 1.0f / (sqrtf(ss) + 1e-8f);
    for (int i = t; i < D_LAT / 4; i += 256) {
        float4 q = ((const float4*)g_q)[i];
        q.x *= inv; q.y *= inv; q.z *= inv; q.w *= inv;
        qsh[i] = q;
    }
    for (int i = t; i < NBINS; i += 256) hist[i] = 0;
    __syncthreads();
    int wg = blockIdx.x * 8 + w;
    for (int base = wg * 2; base < N_MEM; base += SIMS_STRIDE) {
        const float4* r0 = (const float4*)(mem + (size_t)base * D_LAT);
        const float4* r1 = (const float4*)(mem + (size_t)(base + 1) * D_LAT);
        float d0 = 0.f, s0 = 0.f, d1 = 0.f, s1 = 0.f;
#pragma unroll
        for (int u = 0; u < 4; u++) {
            float4 a = r0[lane + 32 * u];
            float4 b = r1[lane + 32 * u];
            float4 q = qsh[lane + 32 * u];
            d0 += a.x * q.x + a.y * q.y + a.z * q.z + a.w * q.w;
            s0 += a.x * a.x + a.y * a.y + a.z * a.z + a.w * a.w;
            d1 += b.x * q.x + b.y * q.y + b.z * q.z + b.w * q.w;
            s1 += b.x * b.x + b.y * b.y + b.z * b.z + b.w * b.w;
        }
        d0 = warp_sum(d0); s0 = warp_sum(s0);
        d1 = warp_sum(d1); s1 = warp_sum(s1);
        if (lane == 0) {
            float v0 = d0 / (sqrtf(s0) + 1e-8f);
            float v1 = d1 / (sqrtf(s1) + 1e-8f);
            g_sims[base] = v0;
            g_sims[base + 1] = v1;
            atomicAdd(&hist[mkey(v0) >> 20], 1u);
            atomicAdd(&hist[mkey(v1) >> 20], 1u);
        }
    }
    __syncthreads();
    for (int i = t; i < NBINS; i += 256) {
        unsigned c = hist[i];
        if (c) atomicAdd(&g_hist[i], c);
    }
    __syncthreads();
    if (t == 0) {
        __threadfence();
        is_last = (atomicAdd(&g_tick1, 1) == SIMS_GRID - 1);
    }
    __syncthreads();
    if (!is_last) return;

    // --- threshold epilogue (only last block) ---
    unsigned s16 = 0;
#pragma unroll
    for (int i = 0; i < 16; i++) s16 += g_hist[t * 16 + i];
    part[t] = s16;
    __syncthreads();
    if (w == 0) {
        unsigned c8 = 0;
#pragma unroll
        for (int i = 0; i < 8; i++) c8 += part[lane * 8 + i];
        unsigned suf = c8;
#pragma unroll
        for (int o = 1; o < 32; o <<= 1) {
            unsigned x = __shfl_down_sync(0xffffffffu, suf, o);
            if (lane + o < 32) suf += x;
        }
        unsigned above = __shfl_down_sync(0xffffffffu, suf, 1);
        if (lane == 31) above = 0;
        unsigned mask = __ballot_sync(0xffffffffu, suf >= 32u);
        int Lstar = 31 - __clz(mask);   // highest lane whose suffix >= 32
        if (lane == Lstar) {
            unsigned cum = above;
            int seg = Lstar * 8 + 7;
            for (; seg > Lstar * 8; seg--) {
                if (cum + part[seg] >= 32u) break;
                cum += part[seg];
            }
            int bin = seg * 16 + 15;
            for (; bin > seg * 16; bin--) {
                cum += g_hist[bin];
                if (cum >= 32u) break;
            }
            g_tkey = ((unsigned)bin) << 20;
        }
    }
}

// ---------------------------------------------------------------------------
// 3) fused filter + select + rerank + final. 256 co-resident blocks x 512 thr
//    (launch_bounds(512,3): 3 blocks/SM x 148 = 444 >= 256 -> spin is safe).
//    Phase A: 131k-thread scan of L2-warm g_sims; ticket; last block runs the
//    exact stable top-32 select (same order as R12) and raises g_flag2.
//    Phase B: block = c*8 + chunk reranks (16 warps x 4 j, 2-way ILP);
//    ticket; last block reduces partials in fixed order and writes top-16.
__global__ void __launch_bounds__(512, 3) k_fr(const float* __restrict__ mem,
                                               const float* __restrict__ W1,
                                               const float* __restrict__ W2,
                                               const float* __restrict__ b2,
                                               float* __restrict__ out,
                                               int out_size) {
    __shared__ float sv[CAP];
    __shared__ int   si[CAP];
    __shared__ float4 cs[D_LAT / 4];
    __shared__ float wacc[16];
    __shared__ int is_last;
    int t = threadIdx.x, blk = blockIdx.x;
    int w = t >> 5, lane = t & 31;

    // --- Phase A: filter scan (1 float4 per thread, +remainder) ---
    unsigned tkey = g_tkey;
    for (int i4 = blk * 512 + t; i4 < N_MEM / 4; i4 += FR_GRID * 512) {
        float4 v = ((const float4*)g_sims)[i4];
        int i = i4 * 4;
        if (mkey(v.x) >= tkey) { int p = atomicAdd(&g_ncand, 1); if (p < CAP) { g_cv[p] = v.x; g_ci[p] = i; } }
        if (mkey(v.y) >= tkey) { int p = atomicAdd(&g_ncand, 1); if (p < CAP) { g_cv[p] = v.y; g_ci[p] = i + 1; } }
        if (mkey(v.z) >= tkey) { int p = atomicAdd(&g_ncand, 1); if (p < CAP) { g_cv[p] = v.z; g_ci[p] = i + 2; } }
        if (mkey(v.w) >= tkey) { int p = atomicAdd(&g_ncand, 1); if (p < CAP) { g_cv[p] = v.w; g_ci[p] = i + 3; } }
    }
    if (t == 0) {
        __threadfence();
        is_last = (atomicAdd(&g_tick2, 1) == FR_GRID - 1);
    }
    __syncthreads();
    if (is_last) {
        int n = g_ncand; if (n > CAP) n = CAP;
        for (int i = t; i < n; i += 512) { sv[i] = g_cv[i]; si[i] = g_ci[i]; }
        __syncthreads();
        if (w == 0) {
            for (int r = 0; r < 32; r++) {
                float bv = -1e30f; int bi = 0x7fffffff, bp = -1;
                for (int i = lane; i < n; i += 32) {
                    float v = sv[i]; int idx = si[i];
                    if (v > bv || (v == bv && idx < bi)) { bv = v; bi = idx; bp = i; }
                }
#pragma unroll
                for (int o = 16; o; o >>= 1) {
                    float ov = __shfl_xor_sync(0xffffffffu, bv, o);
                    int oi = __shfl_xor_sync(0xffffffffu, bi, o);
                    int op = __shfl_xor_sync(0xffffffffu, bp, o);
                    if (ov > bv || (ov == bv && oi < bi)) { bv = ov; bi = oi; bp = op; }
                }
                if (lane == 0) {
                    g_cand[r] = bi;
                    if (bp >= 0) sv[bp] = -1e30f;
                }
                __syncwarp();
            }
            if (lane == 0) { __threadfence(); atomicExch(&g_flag2, 1); }
        }
        __syncthreads();
    }

    // --- grid sync: wait for candidates (all 256 blocks co-resident) ---
    if (t == 0) {
        while (atomicAdd(&g_flag2, 0) == 0) __nanosleep(32);
        __threadfence();
    }
    __syncthreads();

    // --- Phase B: rerank, block = c*8 + chunk (R12 structure) ---
    int c = blk >> 3, chunk = blk & 7;
    int cidx = g_cand[c];
    for (int i = t; i < D_LAT / 4; i += 512)
        cs[i] = ((const float4*)(mem + (size_t)cidx * D_LAT))[i];
    __syncthreads();
    float acc = 0.f;
#pragma unroll
    for (int jj = 0; jj < 4; jj += 2) {
        int j0 = chunk * 64 + w * 4 + jj, j1 = j0 + 1;
        const float4* p0 = (const float4*)(W1 + (size_t)j0 * (2 * D_LAT) + D_LAT);
        const float4* p1 = (const float4*)(W1 + (size_t)j1 * (2 * D_LAT) + D_LAT);
        float d0 = 0.f, d1 = 0.f;
#pragma unroll
        for (int u = 0; u < 4; u++) {
            float4 a = p0[lane + 32 * u];
            float4 b = p1[lane + 32 * u];
            float4 q = cs[lane + 32 * u];
            d0 += a.x * q.x + a.y * q.y + a.z * q.z + a.w * q.w;
            d1 += b.x * q.x + b.y * q.y + b.z * q.z + b.w * q.w;
        }
        d0 = warp_sum(d0); d1 = warp_sum(d1);
        if (lane == 0) {
            float h0 = g_aj[j0] + d0; if (h0 > 0.f) acc += h0 * W2[j0];
            float h1 = g_aj[j1] + d1; if (h1 > 0.f) acc += h1 * W2[j1];
        }
    }
    if (lane == 0) wacc[w] = acc;
    __syncthreads();
    if (t == 0) {
        float s = 0.f;
#pragma unroll
        for (int i = 0; i < 16; i++) s += wacc[i];
        g_rpart[blk] = s;
        __threadfence();
        is_last = (atomicAdd(&g_tick3, 1) == FR_GRID - 1);
    }
    __syncthreads();
    if (!is_last) return;

    // --- final epilogue: parallel partial load + fixed-order reduce + top-16
    __shared__ float pr[FR_GRID];
    __shared__ float fsc[32];
    __shared__ int   fid[32];
    if (t < FR_GRID) pr[t] = g_rpart[t];
    __syncthreads();
    if (w == 0) {
        float s = 0.f;
#pragma unroll
        for (int p = 0; p < 8; p++) s += pr[lane * 8 + p];
        fsc[lane] = s + b2[0];
        fid[lane] = g_cand[lane];
        __syncwarp();
        if (lane == 0) {
            for (int r = 0; r < 16; r++) {
                float bv = -1e30f; int bp = 0;
                for (int k = 0; k < 32; k++)
                    if (fsc[k] > bv) { bv = fsc[k]; bp = k; }
                if (r < out_size)      out[r]      = bv;
                if (16 + r < out_size) out[16 + r] = (float)fid[bp];
                fsc[bp] = -1e30f;
            }
        }
    }
}

// ---------------------------------------------------------------------------
extern "C" void kernel_launch(void* const* d_in, const int* in_sizes, int n_in,
                              void* d_out, int out_size) {
    const float* query  = (const float*)d_in[0];
    const float* memory = (const float*)d_in[1];
    const float* Wp     = (const float*)d_in[2];
    const float* bp     = (const float*)d_in[3];
    const float* W1     = (const float*)d_in[4];
    const float* b1     = (const float*)d_in[5];
    const float* W2     = (const float*)d_in[6];
    const float* b2     = (const float*)d_in[7];
    (void)in_sizes; (void)n_in;

    k_proj<<<64, 256>>>(query, Wp, bp);
    k_sims<<<SIMS_GRID, 256>>>(memory, W1, b1);
    k_fr  <<<FR_GRID, 512>>>(memory, W1, W2, b2, (float*)d_out, out_size);
}